// round 1
// baseline (speedup 1.0000x reference)
#include <cuda_runtime.h>
#include <cuda_bf16.h>
#include <cstdint>

// Problem shape (fixed): B=4, S=8192 -> M=32768 tokens, H=1024, I=4096, fp32.
#define M_TOK 32768
#define HDIM  1024
#define IDIM  4096

// ---------------------------------------------------------------------------
// Scratch (device globals; no allocation allowed)
// ---------------------------------------------------------------------------
__device__ float g_xnorm[(size_t)M_TOK * HDIM];   // 128 MB
__device__ float g_resadd[(size_t)M_TOK * HDIM];  // 128 MB
__device__ float g_h[(size_t)M_TOK * IDIM];       // 512 MB

// ---------------------------------------------------------------------------
// Kernel 1: fused bias + residual add + LayerNorm
// one block per row (H=1024), 256 threads x 4 floats
// ---------------------------------------------------------------------------
__global__ void __launch_bounds__(256) fused_add_ln(
    const float* __restrict__ inp, const float* __restrict__ resid,
    const float* __restrict__ bias, const float* __restrict__ gw,
    const float* __restrict__ gb, float* __restrict__ xn,
    float* __restrict__ ra)
{
    const int row = blockIdx.x;
    const int t = threadIdx.x;
    const size_t base = (size_t)row * HDIM + t * 4;

    float4 x = *(const float4*)(inp + base);
    float4 r = *(const float4*)(resid + base);
    float4 b = *(const float4*)(bias + t * 4);

    float4 s;
    s.x = x.x + b.x + r.x;
    s.y = x.y + b.y + r.y;
    s.z = x.z + b.z + r.z;
    s.w = x.w + b.w + r.w;
    *(float4*)(ra + base) = s;

    float sum = s.x + s.y + s.z + s.w;
    float sq  = s.x * s.x + s.y * s.y + s.z * s.z + s.w * s.w;

    // warp reduce
    #pragma unroll
    for (int o = 16; o > 0; o >>= 1) {
        sum += __shfl_xor_sync(0xFFFFFFFFu, sum, o);
        sq  += __shfl_xor_sync(0xFFFFFFFFu, sq, o);
    }
    __shared__ float red[16];
    const int warp = t >> 5, lane = t & 31;
    if (lane == 0) { red[warp] = sum; red[8 + warp] = sq; }
    __syncthreads();
    if (t == 0) {
        float s0 = 0.f, q0 = 0.f;
        #pragma unroll
        for (int i = 0; i < 8; i++) { s0 += red[i]; q0 += red[8 + i]; }
        red[0] = s0; red[8] = q0;
    }
    __syncthreads();
    const float mean = red[0] * (1.0f / HDIM);
    const float var  = red[8] * (1.0f / HDIM) - mean * mean;
    const float rstd = rsqrtf(var + 1e-5f);

    float4 w = *(const float4*)(gw + t * 4);
    float4 be = *(const float4*)(gb + t * 4);
    float4 o;
    o.x = (s.x - mean) * rstd * w.x + be.x;
    o.y = (s.y - mean) * rstd * w.y + be.y;
    o.z = (s.z - mean) * rstd * w.z + be.z;
    o.w = (s.w - mean) * rstd * w.w + be.w;
    *(float4*)(xn + base) = o;
}

// ---------------------------------------------------------------------------
// TF32 GEMM: C[M,N] = A[M,K] @ B[K,N] (+bias, +optional GELU / +residual)
// 128x128x32 tiles, cp.async double buffer, mma.sync.m16n8k8 tf32
// ---------------------------------------------------------------------------
#define BM 128
#define BN 128
#define BK 32
#define AST (BK + 4)    // A smem row stride (floats): conflict-free layout
#define BST (BN + 8)    // B smem row stride (floats)
#define A_STAGE (BM * AST)   // 4608 floats
#define B_STAGE (BK * BST)   // 4352 floats
#define SMEM_BYTES ((2 * (A_STAGE + B_STAGE)) * 4)  // 71680

__device__ __forceinline__ void cp_async16(uint32_t smem_addr, const void* gptr) {
    asm volatile("cp.async.cg.shared.global [%0], [%1], 16;\n"
                 :: "r"(smem_addr), "l"(gptr));
}

__device__ __forceinline__ void mma_tf32(float c[4], const uint32_t a[4], const uint32_t b[2]) {
    asm volatile(
        "mma.sync.aligned.m16n8k8.row.col.f32.tf32.tf32.f32 "
        "{%0,%1,%2,%3}, {%4,%5,%6,%7}, {%8,%9}, {%0,%1,%2,%3};\n"
        : "+f"(c[0]), "+f"(c[1]), "+f"(c[2]), "+f"(c[3])
        : "r"(a[0]), "r"(a[1]), "r"(a[2]), "r"(a[3]),
          "r"(b[0]), "r"(b[1]));
}

__device__ __forceinline__ float gelu_tanh(float v) {
    float c = 0.7978845608028654f * (v + 0.044715f * v * v * v);
    return 0.5f * v * (1.0f + tanhf(c));
}

template <bool GELU>
__global__ void __launch_bounds__(256) gemm_tf32(
    const float* __restrict__ A, const float* __restrict__ B,
    const float* __restrict__ bias, const float* __restrict__ res,
    float* __restrict__ C, int N, int K)
{
    extern __shared__ float sm[];
    float* As0 = sm;                 // [2][A_STAGE]
    float* Bs0 = sm + 2 * A_STAGE;   // [2][B_STAGE]

    const int tid = threadIdx.x;
    const int row0 = blockIdx.y * BM;
    const int col0 = blockIdx.x * BN;

    // loader thread mapping
    const int a_c4 = tid & 7;    // 8 float4 per A row (BK=32)
    const int a_r  = tid >> 3;   // 32 rows per pass, 4 passes
    const int b_c4 = tid & 31;   // 32 float4 per B row (BN=128)
    const int b_r  = tid >> 5;   // 8 rows per pass, 4 passes

    // warp/lane mapping for mma: 8 warps as 4(M) x 2(N); warp tile 32x64
    const int warp = tid >> 5, lane = tid & 31;
    const int wm = warp & 3, wn = warp >> 2;
    const int g = lane >> 2, tq = lane & 3;

    float acc[2][8][4];
    #pragma unroll
    for (int mi = 0; mi < 2; mi++)
        #pragma unroll
        for (int j = 0; j < 8; j++)
            #pragma unroll
            for (int q = 0; q < 4; q++) acc[mi][j][q] = 0.0f;

    const int nK = K / BK;

    auto load_tile = [&](int kt, int s) {
        const float* Ag = A + (size_t)row0 * K + kt * BK;
        float* As = As0 + s * A_STAGE;
        #pragma unroll
        for (int i = 0; i < 4; i++) {
            int r = a_r + 32 * i;
            uint32_t dst = (uint32_t)__cvta_generic_to_shared(As + r * AST + a_c4 * 4);
            cp_async16(dst, Ag + (size_t)r * K + a_c4 * 4);
        }
        const float* Bg = B + (size_t)(kt * BK) * N + col0;
        float* Bs = Bs0 + s * B_STAGE;
        #pragma unroll
        for (int i = 0; i < 4; i++) {
            int r = b_r + 8 * i;
            uint32_t dst = (uint32_t)__cvta_generic_to_shared(Bs + r * BST + b_c4 * 4);
            cp_async16(dst, Bg + (size_t)r * N + b_c4 * 4);
        }
        asm volatile("cp.async.commit_group;\n");
    };

    load_tile(0, 0);

    for (int kt = 0; kt < nK; kt++) {
        const int s = kt & 1;
        if (kt + 1 < nK) {
            load_tile(kt + 1, s ^ 1);
            asm volatile("cp.async.wait_group 1;\n");
        } else {
            asm volatile("cp.async.wait_group 0;\n");
        }
        __syncthreads();

        const uint32_t* AsU = (const uint32_t*)(As0 + s * A_STAGE);
        const uint32_t* BsU = (const uint32_t*)(Bs0 + s * B_STAGE);

        #pragma unroll
        for (int kk = 0; kk < BK; kk += 8) {
            uint32_t a[2][4];
            #pragma unroll
            for (int mi = 0; mi < 2; mi++) {
                int mb = wm * 32 + mi * 16;
                a[mi][0] = AsU[(mb + g) * AST + kk + tq];
                a[mi][1] = AsU[(mb + g + 8) * AST + kk + tq];
                a[mi][2] = AsU[(mb + g) * AST + kk + tq + 4];
                a[mi][3] = AsU[(mb + g + 8) * AST + kk + tq + 4];
            }
            uint32_t b[8][2];
            #pragma unroll
            for (int j = 0; j < 8; j++) {
                int nb = wn * 64 + j * 8 + g;
                b[j][0] = BsU[(kk + tq) * BST + nb];
                b[j][1] = BsU[(kk + tq + 4) * BST + nb];
            }
            #pragma unroll
            for (int mi = 0; mi < 2; mi++)
                #pragma unroll
                for (int j = 0; j < 8; j++)
                    mma_tf32(acc[mi][j], a[mi], b[j]);
        }
        __syncthreads();
    }

    // Epilogue
    #pragma unroll
    for (int mi = 0; mi < 2; mi++) {
        const int r0 = row0 + wm * 32 + mi * 16 + g;
        const int r1 = r0 + 8;
        #pragma unroll
        for (int j = 0; j < 8; j++) {
            const int c = col0 + wn * 64 + j * 8 + tq * 2;
            const float b0 = bias[c], b1 = bias[c + 1];
            float v00 = acc[mi][j][0] + b0;
            float v01 = acc[mi][j][1] + b1;
            float v10 = acc[mi][j][2] + b0;
            float v11 = acc[mi][j][3] + b1;
            if (GELU) {
                v00 = gelu_tanh(v00); v01 = gelu_tanh(v01);
                v10 = gelu_tanh(v10); v11 = gelu_tanh(v11);
            } else {
                const float2 ra0 = *(const float2*)(res + (size_t)r0 * N + c);
                const float2 ra1 = *(const float2*)(res + (size_t)r1 * N + c);
                v00 += ra0.x; v01 += ra0.y;
                v10 += ra1.x; v11 += ra1.y;
            }
            *(float2*)(C + (size_t)r0 * N + c) = make_float2(v00, v01);
            *(float2*)(C + (size_t)r1 * N + c) = make_float2(v10, v11);
        }
    }
}

// ---------------------------------------------------------------------------
// Launch
// ---------------------------------------------------------------------------
extern "C" void kernel_launch(void* const* d_in, const int* in_sizes, int n_in,
                              void* d_out, int out_size)
{
    const float* input    = (const float*)d_in[0];
    const float* residual = (const float*)d_in[1];
    // d_in[2] (residual_norm) is unused by the reference
    const float* bias     = (const float*)d_in[3];
    const float* attn_nw  = (const float*)d_in[4];
    const float* attn_nb  = (const float*)d_in[5];
    const float* inter_w  = (const float*)d_in[6];
    const float* inter_b  = (const float*)d_in[7];
    const float* output_w = (const float*)d_in[8];
    const float* output_b = (const float*)d_in[9];
    float* out = (float*)d_out;

    float *xn, *ra, *hbuf;
    cudaGetSymbolAddress((void**)&xn, g_xnorm);
    cudaGetSymbolAddress((void**)&ra, g_resadd);
    cudaGetSymbolAddress((void**)&hbuf, g_h);

    cudaFuncSetAttribute(gemm_tf32<true>,
                         cudaFuncAttributeMaxDynamicSharedMemorySize, SMEM_BYTES);
    cudaFuncSetAttribute(gemm_tf32<false>,
                         cudaFuncAttributeMaxDynamicSharedMemorySize, SMEM_BYTES);

    // 1) fused bias + residual + LN
    fused_add_ln<<<M_TOK, 256>>>(input, residual, bias, attn_nw, attn_nb, xn, ra);

    // 2) h = gelu(x @ inter_w + inter_b)   [32768,4096] = [32768,1024]@[1024,4096]
    gemm_tf32<true><<<dim3(IDIM / BN, M_TOK / BM), 256, SMEM_BYTES>>>(
        xn, inter_w, inter_b, nullptr, hbuf, IDIM, HDIM);

    // 3) out = h @ output_w + output_b + residual_add
    gemm_tf32<false><<<dim3(HDIM / BN, M_TOK / BM), 256, SMEM_BYTES>>>(
        hbuf, output_w, output_b, ra, out, HDIM, IDIM);
}

// round 3
// speedup vs baseline: 1.1737x; 1.1737x over previous
#include <cuda_runtime.h>
#include <cuda_bf16.h>
#include <cstdint>

// Problem shape (fixed): B=4, S=8192 -> M=32768 tokens, H=1024, I=4096, fp32.
#define M_TOK 32768
#define HDIM  1024
#define IDIM  4096

// ---------------------------------------------------------------------------
// Scratch (device globals; no allocation allowed)
// ---------------------------------------------------------------------------
__device__ float g_xnorm[(size_t)M_TOK * HDIM];   // 128 MB
__device__ float g_resadd[(size_t)M_TOK * HDIM];  // 128 MB
__device__ float g_h[(size_t)M_TOK * IDIM];       // 512 MB
__device__ float g_wt1[(size_t)IDIM * HDIM];      // inter_w^T  [I,H]
__device__ float g_wt2[(size_t)HDIM * IDIM];      // output_w^T [H,I]

// ---------------------------------------------------------------------------
// Helpers
// ---------------------------------------------------------------------------
__device__ __forceinline__ void cp_async16(uint32_t smem_addr, const void* gptr) {
    asm volatile("cp.async.cg.shared.global [%0], [%1], 16;\n"
                 :: "r"(smem_addr), "l"(gptr));
}

// ldmatrix x4 (b16 view). On b32 data each reg = one 8x4-b32 matrix fragment:
// thread t holds b32 element (t/4, t%4) of the addressed 8-row x 16-byte tile.
__device__ __forceinline__ void ldsm4(uint32_t r[4], uint32_t addr) {
    asm volatile("ldmatrix.sync.aligned.m8n8.x4.shared.b16 {%0,%1,%2,%3}, [%4];"
                 : "=r"(r[0]), "=r"(r[1]), "=r"(r[2]), "=r"(r[3]) : "r"(addr));
}

__device__ __forceinline__ void mma_tf32(float c[4], const uint32_t a[4],
                                         uint32_t b0, uint32_t b1) {
    asm volatile(
        "mma.sync.aligned.m16n8k8.row.col.f32.tf32.tf32.f32 "
        "{%0,%1,%2,%3}, {%4,%5,%6,%7}, {%8,%9}, {%0,%1,%2,%3};\n"
        : "+f"(c[0]), "+f"(c[1]), "+f"(c[2]), "+f"(c[3])
        : "r"(a[0]), "r"(a[1]), "r"(a[2]), "r"(a[3]), "r"(b0), "r"(b1));
}

__device__ __forceinline__ float tanh_approx(float x) {
    float y;
    asm("tanh.approx.f32 %0, %1;" : "=f"(y) : "f"(x));
    return y;
}
__device__ __forceinline__ float gelu_tanh(float v) {
    float c = 0.7978845608028654f * (v + 0.044715f * v * v * v);
    return 0.5f * v * (1.0f + tanh_approx(c));
}

// ---------------------------------------------------------------------------
// Kernel 1: fused bias + residual add + LayerNorm (HBM-bound, ~80% of peak)
// ---------------------------------------------------------------------------
__global__ void __launch_bounds__(256) fused_add_ln(
    const float* __restrict__ inp, const float* __restrict__ resid,
    const float* __restrict__ bias, const float* __restrict__ gw,
    const float* __restrict__ gb, float* __restrict__ xn,
    float* __restrict__ ra)
{
    const int row = blockIdx.x;
    const int t = threadIdx.x;
    const size_t base = (size_t)row * HDIM + t * 4;

    float4 x = *(const float4*)(inp + base);
    float4 r = *(const float4*)(resid + base);
    float4 b = *(const float4*)(bias + t * 4);

    float4 s;
    s.x = x.x + b.x + r.x;
    s.y = x.y + b.y + r.y;
    s.z = x.z + b.z + r.z;
    s.w = x.w + b.w + r.w;
    *(float4*)(ra + base) = s;

    float sum = s.x + s.y + s.z + s.w;
    float sq  = s.x * s.x + s.y * s.y + s.z * s.z + s.w * s.w;

    #pragma unroll
    for (int o = 16; o > 0; o >>= 1) {
        sum += __shfl_xor_sync(0xFFFFFFFFu, sum, o);
        sq  += __shfl_xor_sync(0xFFFFFFFFu, sq, o);
    }
    __shared__ float red[16];
    const int warp = t >> 5, lane = t & 31;
    if (lane == 0) { red[warp] = sum; red[8 + warp] = sq; }
    __syncthreads();
    if (t == 0) {
        float s0 = 0.f, q0 = 0.f;
        #pragma unroll
        for (int i = 0; i < 8; i++) { s0 += red[i]; q0 += red[8 + i]; }
        red[0] = s0; red[8] = q0;
    }
    __syncthreads();
    const float mean = red[0] * (1.0f / HDIM);
    const float var  = red[8] * (1.0f / HDIM) - mean * mean;
    const float rstd = rsqrtf(var + 1e-5f);

    float4 w = *(const float4*)(gw + t * 4);
    float4 be = *(const float4*)(gb + t * 4);
    float4 o;
    o.x = (s.x - mean) * rstd * w.x + be.x;
    o.y = (s.y - mean) * rstd * w.y + be.y;
    o.z = (s.z - mean) * rstd * w.z + be.z;
    o.w = (s.w - mean) * rstd * w.w + be.w;
    *(float4*)(xn + base) = o;
}

// ---------------------------------------------------------------------------
// Kernel: 32x32 tiled transpose (out[c][r] = in[r][c])
// ---------------------------------------------------------------------------
__global__ void __launch_bounds__(256) transpose32(
    const float* __restrict__ in, float* __restrict__ out, int R, int C)
{
    __shared__ float t[32][33];
    const int c0 = blockIdx.x * 32, r0 = blockIdx.y * 32;
    #pragma unroll
    for (int i = threadIdx.y; i < 32; i += 8)
        t[i][threadIdx.x] = in[(size_t)(r0 + i) * C + c0 + threadIdx.x];
    __syncthreads();
    #pragma unroll
    for (int i = threadIdx.y; i < 32; i += 8)
        out[(size_t)(c0 + i) * R + r0 + threadIdx.x] = t[threadIdx.x][i];
}

// ---------------------------------------------------------------------------
// TF32 GEMM v2: C[M,N] = A[M,K] @ Bt[N,K]^T (+bias, +GELU or +residual)
// CTA tile 128x256x32, 8 warps (2x4), warp tile 64x64.
// Both operands K-major in SMEM; ldmatrix.x4 fragment loads for A and B.
// 3-stage cp.async pipeline.
// ---------------------------------------------------------------------------
#define BM 128
#define BN 256
#define BK 32
#define KST 36                       // row stride in floats (32 + 4 pad)
#define A_FLOATS (BM * KST)          // 4608
#define B_FLOATS (BN * KST)          // 9216
#define STAGE_FLOATS (A_FLOATS + B_FLOATS)   // 13824
#define NSTG 3
#define SMEM_BYTES (NSTG * STAGE_FLOATS * 4) // 165888

template <bool GELU>
__global__ void __launch_bounds__(256, 1) gemm_tf32_v2(
    const float* __restrict__ A, const float* __restrict__ Bt,
    const float* __restrict__ bias, const float* __restrict__ res,
    float* __restrict__ C, int N, int K)
{
    extern __shared__ float smf[];
    const uint32_t sm0 = (uint32_t)__cvta_generic_to_shared(smf);

    const int tid = threadIdx.x;
    const int warp = tid >> 5, lane = tid & 31;
    const int wm = warp >> 2, wn = warp & 3;     // 2 (M) x 4 (N)
    const int row0 = blockIdx.y * BM;
    const int col0 = blockIdx.x * BN;
    const int g = lane >> 2, tq = lane & 3;

    // ldmatrix per-thread address components
    const int a_row = wm * 64 + (lane & 15);
    const int a_col = (lane >> 4) * 4;
    const int b_row = wn * 64 + ((lane & 7) | ((lane >> 1) & 8));
    const int b_col = ((lane >> 3) & 1) * 4;

    float acc[4][8][4];
    #pragma unroll
    for (int mi = 0; mi < 4; mi++)
        #pragma unroll
        for (int j = 0; j < 8; j++)
            #pragma unroll
            for (int q = 0; q < 4; q++) acc[mi][j][q] = 0.0f;

    const int nK = K / BK;

    auto load_stage = [&](int kt, int s) {
        float* As = smf + s * STAGE_FLOATS;
        float* Bs = As + A_FLOATS;
        const float* Ag = A + (size_t)row0 * K + kt * BK;
        const float* Bg = Bt + (size_t)col0 * K + kt * BK;
        #pragma unroll
        for (int i = 0; i < 4; i++) {          // A: 1024 chunks of 16B
            int c = tid + 256 * i;
            int r = c >> 3, o = (c & 7) * 4;
            cp_async16((uint32_t)__cvta_generic_to_shared(As + r * KST + o),
                       Ag + (size_t)r * K + o);
        }
        #pragma unroll
        for (int i = 0; i < 8; i++) {          // B: 2048 chunks of 16B
            int c = tid + 256 * i;
            int r = c >> 3, o = (c & 7) * 4;
            cp_async16((uint32_t)__cvta_generic_to_shared(Bs + r * KST + o),
                       Bg + (size_t)r * K + o);
        }
        asm volatile("cp.async.commit_group;\n");
    };

    load_stage(0, 0);
    load_stage(1, 1);
    load_stage(2, 2);

    int s = 0;
    for (int kt = 0; kt < nK; kt++) {
        asm volatile("cp.async.wait_group 2;\n");
        __syncthreads();

        const uint32_t As_u = sm0 + (s * STAGE_FLOATS) * 4;
        const uint32_t Bs_u = As_u + A_FLOATS * 4;
        const uint32_t a_addr = As_u + (a_row * KST + a_col) * 4;
        const uint32_t b_addr = Bs_u + (b_row * KST + b_col) * 4;

        #pragma unroll
        for (int kk = 0; kk < BK; kk += 8) {
            uint32_t af[4][4], bf[4][4];
            #pragma unroll
            for (int mi = 0; mi < 4; mi++)
                ldsm4(af[mi], a_addr + (mi * 16 * KST + kk) * 4);
            #pragma unroll
            for (int p = 0; p < 4; p++)
                ldsm4(bf[p], b_addr + (p * 16 * KST + kk) * 4);
            #pragma unroll
            for (int mi = 0; mi < 4; mi++)
                #pragma unroll
                for (int j = 0; j < 8; j++)
                    mma_tf32(acc[mi][j], af[mi],
                             bf[j >> 1][(j & 1) * 2], bf[j >> 1][(j & 1) * 2 + 1]);
        }
        __syncthreads();
        if (kt + 3 < nK) load_stage(kt + 3, s);
        s = (s == 2) ? 0 : s + 1;
    }

    // Epilogue: direct register -> gmem (float2 per c-pair)
    #pragma unroll
    for (int mi = 0; mi < 4; mi++) {
        const int r0 = row0 + wm * 64 + mi * 16 + g;
        const int r1 = r0 + 8;
        #pragma unroll
        for (int j = 0; j < 8; j++) {
            const int c = col0 + wn * 64 + j * 8 + tq * 2;
            const float b0 = bias[c], b1 = bias[c + 1];
            float v00 = acc[mi][j][0] + b0;
            float v01 = acc[mi][j][1] + b1;
            float v10 = acc[mi][j][2] + b0;
            float v11 = acc[mi][j][3] + b1;
            if (GELU) {
                v00 = gelu_tanh(v00); v01 = gelu_tanh(v01);
                v10 = gelu_tanh(v10); v11 = gelu_tanh(v11);
            } else {
                const float2 ra0 = *(const float2*)(res + (size_t)r0 * N + c);
                const float2 ra1 = *(const float2*)(res + (size_t)r1 * N + c);
                v00 += ra0.x; v01 += ra0.y;
                v10 += ra1.x; v11 += ra1.y;
            }
            *(float2*)(C + (size_t)r0 * N + c) = make_float2(v00, v01);
            *(float2*)(C + (size_t)r1 * N + c) = make_float2(v10, v11);
        }
    }
}

// ---------------------------------------------------------------------------
// Launch
// ---------------------------------------------------------------------------
extern "C" void kernel_launch(void* const* d_in, const int* in_sizes, int n_in,
                              void* d_out, int out_size)
{
    const float* input    = (const float*)d_in[0];
    const float* residual = (const float*)d_in[1];
    const float* bias     = (const float*)d_in[3];
    const float* attn_nw  = (const float*)d_in[4];
    const float* attn_nb  = (const float*)d_in[5];
    const float* inter_w  = (const float*)d_in[6];
    const float* inter_b  = (const float*)d_in[7];
    const float* output_w = (const float*)d_in[8];
    const float* output_b = (const float*)d_in[9];
    float* out = (float*)d_out;

    float *xn, *ra, *hbuf, *wt1, *wt2;
    cudaGetSymbolAddress((void**)&xn,   g_xnorm);
    cudaGetSymbolAddress((void**)&ra,   g_resadd);
    cudaGetSymbolAddress((void**)&hbuf, g_h);
    cudaGetSymbolAddress((void**)&wt1,  g_wt1);
    cudaGetSymbolAddress((void**)&wt2,  g_wt2);

    cudaFuncSetAttribute(gemm_tf32_v2<true>,
                         cudaFuncAttributeMaxDynamicSharedMemorySize, SMEM_BYTES);
    cudaFuncSetAttribute(gemm_tf32_v2<false>,
                         cudaFuncAttributeMaxDynamicSharedMemorySize, SMEM_BYTES);

    // weight transposes (K-major B for ldmatrix; tiny: ~8us)
    transpose32<<<dim3(IDIM / 32, HDIM / 32), dim3(32, 8)>>>(inter_w,  wt1, HDIM, IDIM);
    transpose32<<<dim3(HDIM / 32, IDIM / 32), dim3(32, 8)>>>(output_w, wt2, IDIM, HDIM);

    // 1) fused bias + residual + LN
    fused_add_ln<<<M_TOK, 256>>>(input, residual, bias, attn_nw, attn_nb, xn, ra);

    // 2) h = gelu(x @ inter_w + inter_b)  [32768,4096]
    gemm_tf32_v2<true><<<dim3(IDIM / BN, M_TOK / BM), 256, SMEM_BYTES>>>(
        xn, wt1, inter_b, nullptr, hbuf, IDIM, HDIM);

    // 3) out = h @ output_w + output_b + residual_add  [32768,1024]
    gemm_tf32_v2<false><<<dim3(HDIM / BN, M_TOK / BM), 256, SMEM_BYTES>>>(
        hbuf, wt2, output_b, ra, out, HDIM, IDIM);
}

// round 4
// speedup vs baseline: 2.1592x; 1.8397x over previous
#include <cuda_runtime.h>
#include <cuda_fp16.h>
#include <cstdint>

// Problem shape (fixed): B=4, S=8192 -> M=32768 tokens, H=1024, I=4096, fp32.
#define M_TOK 32768
#define HDIM  1024
#define IDIM  4096

// ---------------------------------------------------------------------------
// Scratch (device globals; no allocation allowed)
// ---------------------------------------------------------------------------
__device__ __half g_xnorm[(size_t)M_TOK * HDIM];  // 64 MB  (LN out, fp16)
__device__ float  g_resadd[(size_t)M_TOK * HDIM]; // 128 MB (pre-norm sum, fp32)
__device__ __half g_h[(size_t)M_TOK * IDIM];      // 256 MB (GELU out, fp16)
__device__ __half g_wt1[(size_t)IDIM * HDIM];     // inter_w^T  [I,H] fp16
__device__ __half g_wt2[(size_t)HDIM * IDIM];     // output_w^T [H,I] fp16

// ---------------------------------------------------------------------------
// Helpers
// ---------------------------------------------------------------------------
__device__ __forceinline__ void cp_async16(uint32_t smem_addr, const void* gptr) {
    asm volatile("cp.async.cg.shared.global [%0], [%1], 16;\n"
                 :: "r"(smem_addr), "l"(gptr));
}

__device__ __forceinline__ void ldsm4(uint32_t r[4], uint32_t addr) {
    asm volatile("ldmatrix.sync.aligned.m8n8.x4.shared.b16 {%0,%1,%2,%3}, [%4];"
                 : "=r"(r[0]), "=r"(r[1]), "=r"(r[2]), "=r"(r[3]) : "r"(addr));
}

// fp16 MMA, fp32 accumulate: D[16,8] += A[16,16] * B[16,8]
__device__ __forceinline__ void mma_f16(float c[4], const uint32_t a[4],
                                        uint32_t b0, uint32_t b1) {
    asm volatile(
        "mma.sync.aligned.m16n8k16.row.col.f32.f16.f16.f32 "
        "{%0,%1,%2,%3}, {%4,%5,%6,%7}, {%8,%9}, {%0,%1,%2,%3};\n"
        : "+f"(c[0]), "+f"(c[1]), "+f"(c[2]), "+f"(c[3])
        : "r"(a[0]), "r"(a[1]), "r"(a[2]), "r"(a[3]), "r"(b0), "r"(b1));
}

__device__ __forceinline__ float tanh_approx(float x) {
    float y;
    asm("tanh.approx.f32 %0, %1;" : "=f"(y) : "f"(x));
    return y;
}
__device__ __forceinline__ float gelu_tanh(float v) {
    float c = 0.7978845608028654f * (v + 0.044715f * v * v * v);
    return 0.5f * v * (1.0f + tanh_approx(c));
}

// ---------------------------------------------------------------------------
// Kernel 1: fused bias + residual add + LayerNorm -> fp16 xnorm + fp32 resadd
// ---------------------------------------------------------------------------
__global__ void __launch_bounds__(256) fused_add_ln(
    const float* __restrict__ inp, const float* __restrict__ resid,
    const float* __restrict__ bias, const float* __restrict__ gw,
    const float* __restrict__ gb, __half* __restrict__ xn,
    float* __restrict__ ra)
{
    const int row = blockIdx.x;
    const int t = threadIdx.x;
    const size_t base = (size_t)row * HDIM + t * 4;

    float4 x = *(const float4*)(inp + base);
    float4 r = *(const float4*)(resid + base);
    float4 b = *(const float4*)(bias + t * 4);

    float4 s;
    s.x = x.x + b.x + r.x;
    s.y = x.y + b.y + r.y;
    s.z = x.z + b.z + r.z;
    s.w = x.w + b.w + r.w;
    *(float4*)(ra + base) = s;

    float sum = s.x + s.y + s.z + s.w;
    float sq  = s.x * s.x + s.y * s.y + s.z * s.z + s.w * s.w;

    #pragma unroll
    for (int o = 16; o > 0; o >>= 1) {
        sum += __shfl_xor_sync(0xFFFFFFFFu, sum, o);
        sq  += __shfl_xor_sync(0xFFFFFFFFu, sq, o);
    }
    __shared__ float red[16];
    const int warp = t >> 5, lane = t & 31;
    if (lane == 0) { red[warp] = sum; red[8 + warp] = sq; }
    __syncthreads();
    if (t == 0) {
        float s0 = 0.f, q0 = 0.f;
        #pragma unroll
        for (int i = 0; i < 8; i++) { s0 += red[i]; q0 += red[8 + i]; }
        red[0] = s0; red[8] = q0;
    }
    __syncthreads();
    const float mean = red[0] * (1.0f / HDIM);
    const float var  = red[8] * (1.0f / HDIM) - mean * mean;
    const float rstd = rsqrtf(var + 1e-5f);

    float4 w = *(const float4*)(gw + t * 4);
    float4 be = *(const float4*)(gb + t * 4);
    float o0 = (s.x - mean) * rstd * w.x + be.x;
    float o1 = (s.y - mean) * rstd * w.y + be.y;
    float o2 = (s.z - mean) * rstd * w.z + be.z;
    float o3 = (s.w - mean) * rstd * w.w + be.w;
    __half2* xo = (__half2*)(xn + base);
    xo[0] = __floats2half2_rn(o0, o1);
    xo[1] = __floats2half2_rn(o2, o3);
}

// ---------------------------------------------------------------------------
// Kernel: 32x32 tiled transpose, fp32 in -> fp16 out (out[c][r] = in[r][c])
// ---------------------------------------------------------------------------
__global__ void __launch_bounds__(256) transpose32h(
    const float* __restrict__ in, __half* __restrict__ out, int R, int C)
{
    __shared__ float t[32][33];
    const int c0 = blockIdx.x * 32, r0 = blockIdx.y * 32;
    #pragma unroll
    for (int i = threadIdx.y; i < 32; i += 8)
        t[i][threadIdx.x] = in[(size_t)(r0 + i) * C + c0 + threadIdx.x];
    __syncthreads();
    #pragma unroll
    for (int i = threadIdx.y; i < 32; i += 8)
        out[(size_t)(c0 + i) * R + r0 + threadIdx.x] = __float2half_rn(t[threadIdx.x][i]);
}

// ---------------------------------------------------------------------------
// FP16 GEMM: C[M,N] = A[M,K] @ Bt[N,K]^T (+bias, +GELU->half or +residual->f32)
// CTA tile 128x256xBK64, 8 warps (2x4), warp tile 64x64, m16n8k16 HMMA.
// 3-stage cp.async pipeline.
// ---------------------------------------------------------------------------
#define BM 128
#define BN 256
#define BKH 64                        // halves per K-slab (128 bytes)
#define KSTH 72                       // smem row stride in halves (64 + 8 pad)
#define A_HALVES (BM * KSTH)          // 9216
#define B_HALVES (BN * KSTH)          // 18432
#define STAGE_HALVES (A_HALVES + B_HALVES)   // 27648
#define NSTG 3
#define SMEM_BYTES (NSTG * STAGE_HALVES * 2) // 165888

template <bool GELU>
__global__ void __launch_bounds__(256, 1) gemm_f16(
    const __half* __restrict__ A, const __half* __restrict__ Bt,
    const float* __restrict__ bias, const float* __restrict__ res,
    void* __restrict__ Cv, int N, int K)
{
    extern __shared__ __half smh[];
    const uint32_t sm0 = (uint32_t)__cvta_generic_to_shared(smh);

    const int tid = threadIdx.x;
    const int warp = tid >> 5, lane = tid & 31;
    const int wm = warp >> 2, wn = warp & 3;     // 2 (M) x 4 (N)
    const int row0 = blockIdx.y * BM;
    const int col0 = blockIdx.x * BN;
    const int g = lane >> 2, tq = lane & 3;

    // ldmatrix per-thread address components (in halves)
    const int a_row = wm * 64 + (lane & 15);
    const int a_k   = (lane >> 4) * 8;
    const int b_row = wn * 64 + ((lane & 7) | ((lane >> 1) & 8));
    const int b_k   = ((lane >> 3) & 1) * 8;

    float acc[4][8][4];
    #pragma unroll
    for (int mi = 0; mi < 4; mi++)
        #pragma unroll
        for (int j = 0; j < 8; j++)
            #pragma unroll
            for (int q = 0; q < 4; q++) acc[mi][j][q] = 0.0f;

    const int nK = K / BKH;

    auto load_stage = [&](int kt, int s) {
        __half* As = smh + s * STAGE_HALVES;
        __half* Bs = As + A_HALVES;
        const __half* Ag = A + (size_t)row0 * K + kt * BKH;
        const __half* Bg = Bt + (size_t)col0 * K + kt * BKH;
        #pragma unroll
        for (int i = 0; i < 4; i++) {          // A: 1024 chunks of 16B (8 halves)
            int c = tid + 256 * i;
            int r = c >> 3, o = (c & 7) * 8;
            cp_async16((uint32_t)__cvta_generic_to_shared(As + r * KSTH + o),
                       Ag + (size_t)r * K + o);
        }
        #pragma unroll
        for (int i = 0; i < 8; i++) {          // B: 2048 chunks of 16B
            int c = tid + 256 * i;
            int r = c >> 3, o = (c & 7) * 8;
            cp_async16((uint32_t)__cvta_generic_to_shared(Bs + r * KSTH + o),
                       Bg + (size_t)r * K + o);
        }
        asm volatile("cp.async.commit_group;\n");
    };

    load_stage(0, 0);
    load_stage(1, 1);
    load_stage(2, 2);

    int s = 0;
    for (int kt = 0; kt < nK; kt++) {
        asm volatile("cp.async.wait_group 2;\n");
        __syncthreads();

        const uint32_t As_u = sm0 + (s * STAGE_HALVES) * 2;
        const uint32_t Bs_u = As_u + A_HALVES * 2;
        const uint32_t a_addr = As_u + (a_row * KSTH + a_k) * 2;
        const uint32_t b_addr = Bs_u + (b_row * KSTH + b_k) * 2;

        #pragma unroll
        for (int kk = 0; kk < BKH; kk += 16) {
            uint32_t af[4][4], bf[4][4];
            #pragma unroll
            for (int mi = 0; mi < 4; mi++)
                ldsm4(af[mi], a_addr + (mi * 16 * KSTH + kk) * 2);
            #pragma unroll
            for (int p = 0; p < 4; p++)
                ldsm4(bf[p], b_addr + (p * 16 * KSTH + kk) * 2);
            #pragma unroll
            for (int mi = 0; mi < 4; mi++)
                #pragma unroll
                for (int j = 0; j < 8; j++)
                    mma_f16(acc[mi][j], af[mi],
                            bf[j >> 1][(j & 1) * 2], bf[j >> 1][(j & 1) * 2 + 1]);
        }
        __syncthreads();
        if (kt + 3 < nK) load_stage(kt + 3, s);
        s = (s == 2) ? 0 : s + 1;
    }

    // Epilogue: register -> gmem
    #pragma unroll
    for (int mi = 0; mi < 4; mi++) {
        const int r0 = row0 + wm * 64 + mi * 16 + g;
        const int r1 = r0 + 8;
        #pragma unroll
        for (int j = 0; j < 8; j++) {
            const int c = col0 + wn * 64 + j * 8 + tq * 2;
            const float b0 = bias[c], b1 = bias[c + 1];
            float v00 = acc[mi][j][0] + b0;
            float v01 = acc[mi][j][1] + b1;
            float v10 = acc[mi][j][2] + b0;
            float v11 = acc[mi][j][3] + b1;
            if (GELU) {
                __half* Ch = (__half*)Cv;
                v00 = gelu_tanh(v00); v01 = gelu_tanh(v01);
                v10 = gelu_tanh(v10); v11 = gelu_tanh(v11);
                *(__half2*)(Ch + (size_t)r0 * N + c) = __floats2half2_rn(v00, v01);
                *(__half2*)(Ch + (size_t)r1 * N + c) = __floats2half2_rn(v10, v11);
            } else {
                float* Cf = (float*)Cv;
                const float2 ra0 = *(const float2*)(res + (size_t)r0 * N + c);
                const float2 ra1 = *(const float2*)(res + (size_t)r1 * N + c);
                v00 += ra0.x; v01 += ra0.y;
                v10 += ra1.x; v11 += ra1.y;
                *(float2*)(Cf + (size_t)r0 * N + c) = make_float2(v00, v01);
                *(float2*)(Cf + (size_t)r1 * N + c) = make_float2(v10, v11);
            }
        }
    }
}

// ---------------------------------------------------------------------------
// Launch
// ---------------------------------------------------------------------------
extern "C" void kernel_launch(void* const* d_in, const int* in_sizes, int n_in,
                              void* d_out, int out_size)
{
    const float* input    = (const float*)d_in[0];
    const float* residual = (const float*)d_in[1];
    const float* bias     = (const float*)d_in[3];
    const float* attn_nw  = (const float*)d_in[4];
    const float* attn_nb  = (const float*)d_in[5];
    const float* inter_w  = (const float*)d_in[6];
    const float* inter_b  = (const float*)d_in[7];
    const float* output_w = (const float*)d_in[8];
    const float* output_b = (const float*)d_in[9];
    float* out = (float*)d_out;

    __half *xn, *hbuf, *wt1, *wt2;
    float *ra;
    cudaGetSymbolAddress((void**)&xn,   g_xnorm);
    cudaGetSymbolAddress((void**)&ra,   g_resadd);
    cudaGetSymbolAddress((void**)&hbuf, g_h);
    cudaGetSymbolAddress((void**)&wt1,  g_wt1);
    cudaGetSymbolAddress((void**)&wt2,  g_wt2);

    cudaFuncSetAttribute(gemm_f16<true>,
                         cudaFuncAttributeMaxDynamicSharedMemorySize, SMEM_BYTES);
    cudaFuncSetAttribute(gemm_f16<false>,
                         cudaFuncAttributeMaxDynamicSharedMemorySize, SMEM_BYTES);

    // weight transposes -> fp16 K-major (tiny)
    transpose32h<<<dim3(IDIM / 32, HDIM / 32), dim3(32, 8)>>>(inter_w,  wt1, HDIM, IDIM);
    transpose32h<<<dim3(HDIM / 32, IDIM / 32), dim3(32, 8)>>>(output_w, wt2, IDIM, HDIM);

    // 1) fused bias + residual + LN
    fused_add_ln<<<M_TOK, 256>>>(input, residual, bias, attn_nw, attn_nb, xn, ra);

    // 2) h = gelu(x @ inter_w + inter_b)  [32768,4096] fp16
    gemm_f16<true><<<dim3(IDIM / BN, M_TOK / BM), 256, SMEM_BYTES>>>(
        xn, wt1, inter_b, nullptr, hbuf, IDIM, HDIM);

    // 3) out = h @ output_w + output_b + residual_add  [32768,1024] fp32
    gemm_f16<false><<<dim3(HDIM / BN, M_TOK / BM), 256, SMEM_BYTES>>>(
        hbuf, wt2, output_b, ra, out, HDIM, IDIM);
}

// round 7
// speedup vs baseline: 2.2830x; 1.0573x over previous
#include <cuda_runtime.h>
#include <cuda_fp16.h>
#include <cstdint>

// Problem shape (fixed): B=4, S=8192 -> M=32768 tokens, H=1024, I=4096, fp32.
#define M_TOK 32768
#define HDIM  1024
#define IDIM  4096

// ---------------------------------------------------------------------------
// Scratch (device globals; no allocation allowed)
// ---------------------------------------------------------------------------
__device__ __half g_xnorm[(size_t)M_TOK * HDIM];  // 64 MB  (LN out, fp16)
__device__ float  g_resadd[(size_t)M_TOK * HDIM]; // 128 MB (pre-norm sum, fp32)
__device__ __half g_h[(size_t)M_TOK * IDIM];      // 256 MB (GELU out, fp16)
__device__ __half g_wt1[(size_t)IDIM * HDIM];     // inter_w^T  [I,H] fp16
__device__ __half g_wt2[(size_t)HDIM * IDIM];     // output_w^T [H,I] fp16

// ---------------------------------------------------------------------------
// Helpers
// ---------------------------------------------------------------------------
__device__ __forceinline__ void cp_async16(uint32_t smem_addr, const void* gptr) {
    asm volatile("cp.async.cg.shared.global [%0], [%1], 16;\n"
                 :: "r"(smem_addr), "l"(gptr));
}

__device__ __forceinline__ void ldsm4(uint32_t r[4], uint32_t addr) {
    asm volatile("ldmatrix.sync.aligned.m8n8.x4.shared.b16 {%0,%1,%2,%3}, [%4];"
                 : "=r"(r[0]), "=r"(r[1]), "=r"(r[2]), "=r"(r[3]) : "r"(addr));
}

// fp16 MMA, fp32 accumulate: D[16,8] += A[16,16] * B[16,8]
__device__ __forceinline__ void mma_f16(float c[4], const uint32_t a[4],
                                        uint32_t b0, uint32_t b1) {
    asm volatile(
        "mma.sync.aligned.m16n8k16.row.col.f32.f16.f16.f32 "
        "{%0,%1,%2,%3}, {%4,%5,%6,%7}, {%8,%9}, {%0,%1,%2,%3};\n"
        : "+f"(c[0]), "+f"(c[1]), "+f"(c[2]), "+f"(c[3])
        : "r"(a[0]), "r"(a[1]), "r"(a[2]), "r"(a[3]), "r"(b0), "r"(b1));
}

__device__ __forceinline__ float tanh_approx(float x) {
    float y;
    asm("tanh.approx.f32 %0, %1;" : "=f"(y) : "f"(x));
    return y;
}
__device__ __forceinline__ float gelu_tanh(float v) {
    float c = 0.7978845608028654f * (v + 0.044715f * v * v * v);
    return 0.5f * v * (1.0f + tanh_approx(c));
}

// ---------------------------------------------------------------------------
// Kernel 1: fused bias + residual add + LayerNorm -> fp16 xnorm + fp32 resadd
// ---------------------------------------------------------------------------
__global__ void __launch_bounds__(256) fused_add_ln(
    const float* __restrict__ inp, const float* __restrict__ resid,
    const float* __restrict__ bias, const float* __restrict__ gw,
    const float* __restrict__ gb, __half* __restrict__ xn,
    float* __restrict__ ra)
{
    const int row = blockIdx.x;
    const int t = threadIdx.x;
    const size_t base = (size_t)row * HDIM + t * 4;

    float4 x = *(const float4*)(inp + base);
    float4 r = *(const float4*)(resid + base);
    float4 b = *(const float4*)(bias + t * 4);

    float4 s;
    s.x = x.x + b.x + r.x;
    s.y = x.y + b.y + r.y;
    s.z = x.z + b.z + r.z;
    s.w = x.w + b.w + r.w;
    *(float4*)(ra + base) = s;

    float sum = s.x + s.y + s.z + s.w;
    float sq  = s.x * s.x + s.y * s.y + s.z * s.z + s.w * s.w;

    #pragma unroll
    for (int o = 16; o > 0; o >>= 1) {
        sum += __shfl_xor_sync(0xFFFFFFFFu, sum, o);
        sq  += __shfl_xor_sync(0xFFFFFFFFu, sq, o);
    }
    __shared__ float red[16];
    const int warp = t >> 5, lane = t & 31;
    if (lane == 0) { red[warp] = sum; red[8 + warp] = sq; }
    __syncthreads();
    if (t == 0) {
        float s0 = 0.f, q0 = 0.f;
        #pragma unroll
        for (int i = 0; i < 8; i++) { s0 += red[i]; q0 += red[8 + i]; }
        red[0] = s0; red[8] = q0;
    }
    __syncthreads();
    const float mean = red[0] * (1.0f / HDIM);
    const float var  = red[8] * (1.0f / HDIM) - mean * mean;
    const float rstd = rsqrtf(var + 1e-5f);

    float4 w = *(const float4*)(gw + t * 4);
    float4 be = *(const float4*)(gb + t * 4);
    float o0 = (s.x - mean) * rstd * w.x + be.x;
    float o1 = (s.y - mean) * rstd * w.y + be.y;
    float o2 = (s.z - mean) * rstd * w.z + be.z;
    float o3 = (s.w - mean) * rstd * w.w + be.w;
    __half2* xo = (__half2*)(xn + base);
    xo[0] = __floats2half2_rn(o0, o1);
    xo[1] = __floats2half2_rn(o2, o3);
}

// ---------------------------------------------------------------------------
// Kernel: 32x32 tiled transpose, fp32 in -> fp16 out (out[c][r] = in[r][c])
// ---------------------------------------------------------------------------
__global__ void __launch_bounds__(256) transpose32h(
    const float* __restrict__ in, __half* __restrict__ out, int R, int C)
{
    __shared__ float t[32][33];
    const int c0 = blockIdx.x * 32, r0 = blockIdx.y * 32;
    #pragma unroll
    for (int i = threadIdx.y; i < 32; i += 8)
        t[i][threadIdx.x] = in[(size_t)(r0 + i) * C + c0 + threadIdx.x];
    __syncthreads();
    #pragma unroll
    for (int i = threadIdx.y; i < 32; i += 8)
        out[(size_t)(c0 + i) * R + r0 + threadIdx.x] = __float2half_rn(t[threadIdx.x][i]);
}

// ---------------------------------------------------------------------------
// FP16 GEMM: C[M,N] = A[M,K] @ Bt[N,K]^T (+bias, +GELU->half or +residual->f32)
// CTA tile 128x128xBK64, 4 warps (2x2), warp tile 64x64, m16n8k16 HMMA.
// 3-stage cp.async pipeline, ONE __syncthreads per k-iter (wait->sync->load->
// compute order: wait_group before sync gives cross-thread visibility; loads
// after sync protect WAR on the reused stage), 2 CTAs/SM.
// ---------------------------------------------------------------------------
#define BM 128
#define BN 128
#define BKH 64                        // halves per K-slab (128 bytes)
#define KSTH 72                       // smem row stride in halves (64 + 8 pad)
#define A_HALVES (BM * KSTH)          // 9216
#define B_HALVES (BN * KSTH)          // 9216
#define STAGE_HALVES (A_HALVES + B_HALVES)   // 18432
#define NSTG 3
#define SMEM_BYTES (NSTG * STAGE_HALVES * 2) // 110592

template <bool GELU>
__global__ void __launch_bounds__(128, 2) gemm_f16(
    const __half* __restrict__ A, const __half* __restrict__ Bt,
    const float* __restrict__ bias, const float* __restrict__ res,
    void* __restrict__ Cv, int N, int K)
{
    extern __shared__ __half smh[];
    const uint32_t sm0 = (uint32_t)__cvta_generic_to_shared(smh);

    const int tid = threadIdx.x;
    const int warp = tid >> 5, lane = tid & 31;
    const int wm = warp >> 1, wn = warp & 1;     // 2 (M) x 2 (N)
    const int row0 = blockIdx.y * BM;
    const int col0 = blockIdx.x * BN;
    const int g = lane >> 2, tq = lane & 3;

    // ldmatrix per-thread address components (in halves)
    const int a_row = wm * 64 + (lane & 15);
    const int a_k   = (lane >> 4) * 8;
    const int b_row = wn * 64 + ((lane & 7) | ((lane >> 1) & 8));
    const int b_k   = ((lane >> 3) & 1) * 8;

    float acc[4][8][4];
    #pragma unroll
    for (int mi = 0; mi < 4; mi++)
        #pragma unroll
        for (int j = 0; j < 8; j++)
            #pragma unroll
            for (int q = 0; q < 4; q++) acc[mi][j][q] = 0.0f;

    const int nK = K / BKH;

    auto load_stage = [&](int kt, int s) {
        __half* As = smh + s * STAGE_HALVES;
        __half* Bs = As + A_HALVES;
        const __half* Ag = A + (size_t)row0 * K + kt * BKH;
        const __half* Bg = Bt + (size_t)col0 * K + kt * BKH;
        #pragma unroll
        for (int i = 0; i < 8; i++) {          // A: 1024 chunks of 16B (8 halves)
            int c = tid + 128 * i;
            int r = c >> 3, o = (c & 7) * 8;
            cp_async16((uint32_t)__cvta_generic_to_shared(As + r * KSTH + o),
                       Ag + (size_t)r * K + o);
        }
        #pragma unroll
        for (int i = 0; i < 8; i++) {          // B: 1024 chunks of 16B
            int c = tid + 128 * i;
            int r = c >> 3, o = (c & 7) * 8;
            cp_async16((uint32_t)__cvta_generic_to_shared(Bs + r * KSTH + o),
                       Bg + (size_t)r * K + o);
        }
        asm volatile("cp.async.commit_group;\n");
    };

    // prefill 2 stages (tiles 0,1 -> 2 groups)
    load_stage(0, 0);
    load_stage(1, 1);

    for (int kt = 0; kt < nK; kt++) {
        const int s = kt % NSTG;
        // tile kt complete in THIS thread (only tile kt+1's group may pend)
        asm volatile("cp.async.wait_group 1;\n");
        // publish all threads' copies of tile kt; also: all threads are done
        // reading stage (kt-1)%NSTG, which is about to be overwritten below
        __syncthreads();
        if (kt + 2 < nK) {
            load_stage(kt + 2, (kt + 2) % NSTG);       // commits 1 group
        } else {
            asm volatile("cp.async.commit_group;\n");  // keep group-count invariant
        }

        const uint32_t As_u = sm0 + (s * STAGE_HALVES) * 2;
        const uint32_t Bs_u = As_u + A_HALVES * 2;
        const uint32_t a_addr = As_u + (a_row * KSTH + a_k) * 2;
        const uint32_t b_addr = Bs_u + (b_row * KSTH + b_k) * 2;

        #pragma unroll
        for (int kk = 0; kk < BKH; kk += 16) {
            uint32_t af[4][4], bf[4][4];
            #pragma unroll
            for (int mi = 0; mi < 4; mi++)
                ldsm4(af[mi], a_addr + (mi * 16 * KSTH + kk) * 2);
            #pragma unroll
            for (int p = 0; p < 4; p++)
                ldsm4(bf[p], b_addr + (p * 16 * KSTH + kk) * 2);
            #pragma unroll
            for (int mi = 0; mi < 4; mi++)
                #pragma unroll
                for (int j = 0; j < 8; j++)
                    mma_f16(acc[mi][j], af[mi],
                            bf[j >> 1][(j & 1) * 2], bf[j >> 1][(j & 1) * 2 + 1]);
        }
    }

    // Epilogue: register -> gmem
    #pragma unroll
    for (int mi = 0; mi < 4; mi++) {
        const int r0 = row0 + wm * 64 + mi * 16 + g;
        const int r1 = r0 + 8;
        #pragma unroll
        for (int j = 0; j < 8; j++) {
            const int c = col0 + wn * 64 + j * 8 + tq * 2;
            const float b0 = bias[c], b1 = bias[c + 1];
            float v00 = acc[mi][j][0] + b0;
            float v01 = acc[mi][j][1] + b1;
            float v10 = acc[mi][j][2] + b0;
            float v11 = acc[mi][j][3] + b1;
            if (GELU) {
                __half* Ch = (__half*)Cv;
                v00 = gelu_tanh(v00); v01 = gelu_tanh(v01);
                v10 = gelu_tanh(v10); v11 = gelu_tanh(v11);
                *(__half2*)(Ch + (size_t)r0 * N + c) = __floats2half2_rn(v00, v01);
                *(__half2*)(Ch + (size_t)r1 * N + c) = __floats2half2_rn(v10, v11);
            } else {
                float* Cf = (float*)Cv;
                const float2 ra0 = *(const float2*)(res + (size_t)r0 * N + c);
                const float2 ra1 = *(const float2*)(res + (size_t)r1 * N + c);
                v00 += ra0.x; v01 += ra0.y;
                v10 += ra1.x; v11 += ra1.y;
                *(float2*)(Cf + (size_t)r0 * N + c) = make_float2(v00, v01);
                *(float2*)(Cf + (size_t)r1 * N + c) = make_float2(v10, v11);
            }
        }
    }
}

// ---------------------------------------------------------------------------
// Launch
// ---------------------------------------------------------------------------
extern "C" void kernel_launch(void* const* d_in, const int* in_sizes, int n_in,
                              void* d_out, int out_size)
{
    const float* input    = (const float*)d_in[0];
    const float* residual = (const float*)d_in[1];
    const float* bias     = (const float*)d_in[3];
    const float* attn_nw  = (const float*)d_in[4];
    const float* attn_nb  = (const float*)d_in[5];
    const float* inter_w  = (const float*)d_in[6];
    const float* inter_b  = (const float*)d_in[7];
    const float* output_w = (const float*)d_in[8];
    const float* output_b = (const float*)d_in[9];
    float* out = (float*)d_out;

    __half *xn, *hbuf, *wt1, *wt2;
    float *ra;
    cudaGetSymbolAddress((void**)&xn,   g_xnorm);
    cudaGetSymbolAddress((void**)&ra,   g_resadd);
    cudaGetSymbolAddress((void**)&hbuf, g_h);
    cudaGetSymbolAddress((void**)&wt1,  g_wt1);
    cudaGetSymbolAddress((void**)&wt2,  g_wt2);

    cudaFuncSetAttribute(gemm_f16<true>,
                         cudaFuncAttributeMaxDynamicSharedMemorySize, SMEM_BYTES);
    cudaFuncSetAttribute(gemm_f16<false>,
                         cudaFuncAttributeMaxDynamicSharedMemorySize, SMEM_BYTES);

    // weight transposes -> fp16 K-major (tiny)
    transpose32h<<<dim3(IDIM / 32, HDIM / 32), dim3(32, 8)>>>(inter_w,  wt1, HDIM, IDIM);
    transpose32h<<<dim3(HDIM / 32, IDIM / 32), dim3(32, 8)>>>(output_w, wt2, IDIM, HDIM);

    // 1) fused bias + residual + LN
    fused_add_ln<<<M_TOK, 256>>>(input, residual, bias, attn_nw, attn_nb, xn, ra);

    // 2) h = gelu(x @ inter_w + inter_b)  [32768,4096] fp16
    gemm_f16<true><<<dim3(IDIM / BN, M_TOK / BM), 128, SMEM_BYTES>>>(
        xn, wt1, inter_b, nullptr, hbuf, IDIM, HDIM);

    // 3) out = h @ output_w + output_b + residual_add  [32768,1024] fp32
    gemm_f16<false><<<dim3(HDIM / BN, M_TOK / BM), 128, SMEM_BYTES>>>(
        hbuf, wt2, output_b, ra, out, HDIM, IDIM);
}

// round 8
// speedup vs baseline: 2.2870x; 1.0017x over previous
#include <cuda_runtime.h>
#include <cuda_fp16.h>
#include <cstdint>

// Problem shape (fixed): B=4, S=8192 -> M=32768 tokens, H=1024, I=4096, fp32.
#define M_TOK 32768
#define HDIM  1024
#define IDIM  4096

// ---------------------------------------------------------------------------
// Scratch (device globals; no allocation allowed)
// ---------------------------------------------------------------------------
__device__ __half g_xnorm[(size_t)M_TOK * HDIM];  // 64 MB  (LN out, fp16)
__device__ float  g_resadd[(size_t)M_TOK * HDIM]; // 128 MB (pre-norm sum, fp32)
__device__ __half g_h[(size_t)M_TOK * IDIM];      // 256 MB (GELU out, fp16)
__device__ __half g_wt1[(size_t)IDIM * HDIM];     // inter_w^T  [I,H] fp16
__device__ __half g_wt2[(size_t)HDIM * IDIM];     // output_w^T [H,I] fp16

// ---------------------------------------------------------------------------
// Helpers
// ---------------------------------------------------------------------------
__device__ __forceinline__ void cp_async16(uint32_t smem_addr, const void* gptr) {
    asm volatile("cp.async.cg.shared.global [%0], [%1], 16;\n"
                 :: "r"(smem_addr), "l"(gptr));
}

__device__ __forceinline__ void ldsm4(uint32_t r[4], uint32_t addr) {
    asm volatile("ldmatrix.sync.aligned.m8n8.x4.shared.b16 {%0,%1,%2,%3}, [%4];"
                 : "=r"(r[0]), "=r"(r[1]), "=r"(r[2]), "=r"(r[3]) : "r"(addr));
}

// fp16 MMA, fp32 accumulate: D[16,8] += A[16,16] * B[16,8]
__device__ __forceinline__ void mma_f16(float c[4], const uint32_t a[4],
                                        uint32_t b0, uint32_t b1) {
    asm volatile(
        "mma.sync.aligned.m16n8k16.row.col.f32.f16.f16.f32 "
        "{%0,%1,%2,%3}, {%4,%5,%6,%7}, {%8,%9}, {%0,%1,%2,%3};\n"
        : "+f"(c[0]), "+f"(c[1]), "+f"(c[2]), "+f"(c[3])
        : "r"(a[0]), "r"(a[1]), "r"(a[2]), "r"(a[3]), "r"(b0), "r"(b1));
}

__device__ __forceinline__ float tanh_approx(float x) {
    float y;
    asm("tanh.approx.f32 %0, %1;" : "=f"(y) : "f"(x));
    return y;
}
__device__ __forceinline__ float gelu_tanh(float v) {
    float c = 0.7978845608028654f * (v + 0.044715f * v * v * v);
    return 0.5f * v * (1.0f + tanh_approx(c));
}

// ---------------------------------------------------------------------------
// Kernel 1: fused bias + residual add + LayerNorm -> fp16 xnorm + fp32 resadd
// ---------------------------------------------------------------------------
__global__ void __launch_bounds__(256) fused_add_ln(
    const float* __restrict__ inp, const float* __restrict__ resid,
    const float* __restrict__ bias, const float* __restrict__ gw,
    const float* __restrict__ gb, __half* __restrict__ xn,
    float* __restrict__ ra)
{
    const int row = blockIdx.x;
    const int t = threadIdx.x;
    const size_t base = (size_t)row * HDIM + t * 4;

    float4 x = *(const float4*)(inp + base);
    float4 r = *(const float4*)(resid + base);
    float4 b = *(const float4*)(bias + t * 4);

    float4 s;
    s.x = x.x + b.x + r.x;
    s.y = x.y + b.y + r.y;
    s.z = x.z + b.z + r.z;
    s.w = x.w + b.w + r.w;
    *(float4*)(ra + base) = s;

    float sum = s.x + s.y + s.z + s.w;
    float sq  = s.x * s.x + s.y * s.y + s.z * s.z + s.w * s.w;

    #pragma unroll
    for (int o = 16; o > 0; o >>= 1) {
        sum += __shfl_xor_sync(0xFFFFFFFFu, sum, o);
        sq  += __shfl_xor_sync(0xFFFFFFFFu, sq, o);
    }
    __shared__ float red[16];
    const int warp = t >> 5, lane = t & 31;
    if (lane == 0) { red[warp] = sum; red[8 + warp] = sq; }
    __syncthreads();
    if (t == 0) {
        float s0 = 0.f, q0 = 0.f;
        #pragma unroll
        for (int i = 0; i < 8; i++) { s0 += red[i]; q0 += red[8 + i]; }
        red[0] = s0; red[8] = q0;
    }
    __syncthreads();
    const float mean = red[0] * (1.0f / HDIM);
    const float var  = red[8] * (1.0f / HDIM) - mean * mean;
    const float rstd = rsqrtf(var + 1e-5f);

    float4 w = *(const float4*)(gw + t * 4);
    float4 be = *(const float4*)(gb + t * 4);
    float o0 = (s.x - mean) * rstd * w.x + be.x;
    float o1 = (s.y - mean) * rstd * w.y + be.y;
    float o2 = (s.z - mean) * rstd * w.z + be.z;
    float o3 = (s.w - mean) * rstd * w.w + be.w;
    __half2* xo = (__half2*)(xn + base);
    xo[0] = __floats2half2_rn(o0, o1);
    xo[1] = __floats2half2_rn(o2, o3);
}

// ---------------------------------------------------------------------------
// Kernel: 32x32 tiled transpose, fp32 in -> fp16 out (out[c][r] = in[r][c])
// ---------------------------------------------------------------------------
__global__ void __launch_bounds__(256) transpose32h(
    const float* __restrict__ in, __half* __restrict__ out, int R, int C)
{
    __shared__ float t[32][33];
    const int c0 = blockIdx.x * 32, r0 = blockIdx.y * 32;
    #pragma unroll
    for (int i = threadIdx.y; i < 32; i += 8)
        t[i][threadIdx.x] = in[(size_t)(r0 + i) * C + c0 + threadIdx.x];
    __syncthreads();
    #pragma unroll
    for (int i = threadIdx.y; i < 32; i += 8)
        out[(size_t)(c0 + i) * R + r0 + threadIdx.x] = __float2half_rn(t[threadIdx.x][i]);
}

// ---------------------------------------------------------------------------
// FP16 GEMM: C[M,N] = A[M,K] @ Bt[N,K]^T (+bias, +GELU->half or +residual->f32)
// CTA tile 128x128xBK64, 4 warps (2x2), warp tile 64x64, m16n8k16 HMMA.
// 3-stage cp.async pipeline, ONE __syncthreads per k-iter, 2 CTAs/SM.
// NEW: explicit double-buffered fragment registers so each warp interleaves
// next-chunk LDSM with current-chunk MMAs (tensor/LSU pipe overlap).
// ---------------------------------------------------------------------------
#define BM 128
#define BN 128
#define BKH 64                        // halves per K-slab (128 bytes)
#define KSTH 72                       // smem row stride in halves (64 + 8 pad)
#define A_HALVES (BM * KSTH)          // 9216
#define B_HALVES (BN * KSTH)          // 9216
#define STAGE_HALVES (A_HALVES + B_HALVES)   // 18432
#define NSTG 3
#define SMEM_BYTES (NSTG * STAGE_HALVES * 2) // 110592

template <bool GELU>
__global__ void __launch_bounds__(128, 2) gemm_f16(
    const __half* __restrict__ A, const __half* __restrict__ Bt,
    const float* __restrict__ bias, const float* __restrict__ res,
    void* __restrict__ Cv, int N, int K)
{
    extern __shared__ __half smh[];
    const uint32_t sm0 = (uint32_t)__cvta_generic_to_shared(smh);

    const int tid = threadIdx.x;
    const int warp = tid >> 5, lane = tid & 31;
    const int wm = warp >> 1, wn = warp & 1;     // 2 (M) x 2 (N)
    const int row0 = blockIdx.y * BM;
    const int col0 = blockIdx.x * BN;
    const int g = lane >> 2, tq = lane & 3;

    // ldmatrix per-thread address components (in halves)
    const int a_row = wm * 64 + (lane & 15);
    const int a_k   = (lane >> 4) * 8;
    const int b_row = wn * 64 + ((lane & 7) | ((lane >> 1) & 8));
    const int b_k   = ((lane >> 3) & 1) * 8;

    float acc[4][8][4];
    #pragma unroll
    for (int mi = 0; mi < 4; mi++)
        #pragma unroll
        for (int j = 0; j < 8; j++)
            #pragma unroll
            for (int q = 0; q < 4; q++) acc[mi][j][q] = 0.0f;

    const int nK = K / BKH;

    auto load_stage = [&](int kt, int s) {
        __half* As = smh + s * STAGE_HALVES;
        __half* Bs = As + A_HALVES;
        const __half* Ag = A + (size_t)row0 * K + kt * BKH;
        const __half* Bg = Bt + (size_t)col0 * K + kt * BKH;
        #pragma unroll
        for (int i = 0; i < 8; i++) {          // A: 1024 chunks of 16B (8 halves)
            int c = tid + 128 * i;
            int r = c >> 3, o = (c & 7) * 8;
            cp_async16((uint32_t)__cvta_generic_to_shared(As + r * KSTH + o),
                       Ag + (size_t)r * K + o);
        }
        #pragma unroll
        for (int i = 0; i < 8; i++) {          // B: 1024 chunks of 16B
            int c = tid + 128 * i;
            int r = c >> 3, o = (c & 7) * 8;
            cp_async16((uint32_t)__cvta_generic_to_shared(Bs + r * KSTH + o),
                       Bg + (size_t)r * K + o);
        }
        asm volatile("cp.async.commit_group;\n");
    };

    // prefill 2 stages (tiles 0,1 -> 2 groups)
    load_stage(0, 0);
    load_stage(1, 1);

    // double-buffered fragment registers
    uint32_t af[2][4][4], bf[2][4][4];

    for (int kt = 0; kt < nK; kt++) {
        const int s = kt % NSTG;
        // tile kt complete in THIS thread (only tile kt+1's group may pend)
        asm volatile("cp.async.wait_group 1;\n");
        // publish all threads' copies of tile kt; also: everyone is done
        // reading stage (kt-1)%NSTG, which gets overwritten below
        __syncthreads();
        if (kt + 2 < nK) {
            load_stage(kt + 2, (kt + 2) % NSTG);       // commits 1 group
        } else {
            asm volatile("cp.async.commit_group;\n");  // keep group-count invariant
        }

        const uint32_t As_u = sm0 + (s * STAGE_HALVES) * 2;
        const uint32_t Bs_u = As_u + A_HALVES * 2;
        const uint32_t a_addr = As_u + (a_row * KSTH + a_k) * 2;
        const uint32_t b_addr = Bs_u + (b_row * KSTH + b_k) * 2;

        // load fragments for kk=0 into buffer 0
        #pragma unroll
        for (int mi = 0; mi < 4; mi++)
            ldsm4(af[0][mi], a_addr + (mi * 16 * KSTH) * 2);
        #pragma unroll
        for (int p = 0; p < 4; p++)
            ldsm4(bf[0][p], b_addr + (p * 16 * KSTH) * 2);

        #pragma unroll
        for (int kk = 0; kk < 4; kk++) {
            const int cur = kk & 1, nxt = cur ^ 1;
            if (kk < 3) {
                // prefetch next chunk's fragments; these LDSMs interleave
                // with the 32 MMAs below (independent register buffers)
                #pragma unroll
                for (int mi = 0; mi < 4; mi++)
                    ldsm4(af[nxt][mi], a_addr + (mi * 16 * KSTH + (kk + 1) * 16) * 2);
                #pragma unroll
                for (int p = 0; p < 4; p++)
                    ldsm4(bf[nxt][p], b_addr + (p * 16 * KSTH + (kk + 1) * 16) * 2);
            }
            #pragma unroll
            for (int mi = 0; mi < 4; mi++)
                #pragma unroll
                for (int j = 0; j < 8; j++)
                    mma_f16(acc[mi][j], af[cur][mi],
                            bf[cur][j >> 1][(j & 1) * 2], bf[cur][j >> 1][(j & 1) * 2 + 1]);
        }
    }

    // Epilogue: register -> gmem
    #pragma unroll
    for (int mi = 0; mi < 4; mi++) {
        const int r0 = row0 + wm * 64 + mi * 16 + g;
        const int r1 = r0 + 8;
        #pragma unroll
        for (int j = 0; j < 8; j++) {
            const int c = col0 + wn * 64 + j * 8 + tq * 2;
            const float b0 = bias[c], b1 = bias[c + 1];
            float v00 = acc[mi][j][0] + b0;
            float v01 = acc[mi][j][1] + b1;
            float v10 = acc[mi][j][2] + b0;
            float v11 = acc[mi][j][3] + b1;
            if (GELU) {
                __half* Ch = (__half*)Cv;
                v00 = gelu_tanh(v00); v01 = gelu_tanh(v01);
                v10 = gelu_tanh(v10); v11 = gelu_tanh(v11);
                *(__half2*)(Ch + (size_t)r0 * N + c) = __floats2half2_rn(v00, v01);
                *(__half2*)(Ch + (size_t)r1 * N + c) = __floats2half2_rn(v10, v11);
            } else {
                float* Cf = (float*)Cv;
                const float2 ra0 = *(const float2*)(res + (size_t)r0 * N + c);
                const float2 ra1 = *(const float2*)(res + (size_t)r1 * N + c);
                v00 += ra0.x; v01 += ra0.y;
                v10 += ra1.x; v11 += ra1.y;
                *(float2*)(Cf + (size_t)r0 * N + c) = make_float2(v00, v01);
                *(float2*)(Cf + (size_t)r1 * N + c) = make_float2(v10, v11);
            }
        }
    }
}

// ---------------------------------------------------------------------------
// Launch
// ---------------------------------------------------------------------------
extern "C" void kernel_launch(void* const* d_in, const int* in_sizes, int n_in,
                              void* d_out, int out_size)
{
    const float* input    = (const float*)d_in[0];
    const float* residual = (const float*)d_in[1];
    const float* bias     = (const float*)d_in[3];
    const float* attn_nw  = (const float*)d_in[4];
    const float* attn_nb  = (const float*)d_in[5];
    const float* inter_w  = (const float*)d_in[6];
    const float* inter_b  = (const float*)d_in[7];
    const float* output_w = (const float*)d_in[8];
    const float* output_b = (const float*)d_in[9];
    float* out = (float*)d_out;

    __half *xn, *hbuf, *wt1, *wt2;
    float *ra;
    cudaGetSymbolAddress((void**)&xn,   g_xnorm);
    cudaGetSymbolAddress((void**)&ra,   g_resadd);
    cudaGetSymbolAddress((void**)&hbuf, g_h);
    cudaGetSymbolAddress((void**)&wt1,  g_wt1);
    cudaGetSymbolAddress((void**)&wt2,  g_wt2);

    cudaFuncSetAttribute(gemm_f16<true>,
                         cudaFuncAttributeMaxDynamicSharedMemorySize, SMEM_BYTES);
    cudaFuncSetAttribute(gemm_f16<false>,
                         cudaFuncAttributeMaxDynamicSharedMemorySize, SMEM_BYTES);

    // weight transposes -> fp16 K-major (tiny)
    transpose32h<<<dim3(IDIM / 32, HDIM / 32), dim3(32, 8)>>>(inter_w,  wt1, HDIM, IDIM);
    transpose32h<<<dim3(HDIM / 32, IDIM / 32), dim3(32, 8)>>>(output_w, wt2, IDIM, HDIM);

    // 1) fused bias + residual + LN
    fused_add_ln<<<M_TOK, 256>>>(input, residual, bias, attn_nw, attn_nb, xn, ra);

    // 2) h = gelu(x @ inter_w + inter_b)  [32768,4096] fp16
    gemm_f16<true><<<dim3(IDIM / BN, M_TOK / BM), 128, SMEM_BYTES>>>(
        xn, wt1, inter_b, nullptr, hbuf, IDIM, HDIM);

    // 3) out = h @ output_w + output_b + residual_add  [32768,1024] fp32
    gemm_f16<false><<<dim3(HDIM / BN, M_TOK / BM), 128, SMEM_BYTES>>>(
        hbuf, wt2, output_b, ra, out, HDIM, IDIM);
}

// round 10
// speedup vs baseline: 2.3365x; 1.0216x over previous
#include <cuda_runtime.h>
#include <cuda_fp16.h>
#include <cstdint>

// Problem shape (fixed): B=4, S=8192 -> M=32768 tokens, H=1024, I=4096, fp32.
#define M_TOK 32768
#define HDIM  1024
#define IDIM  4096

// ---------------------------------------------------------------------------
// Scratch (device globals; no allocation allowed)
// ---------------------------------------------------------------------------
__device__ __half g_xnorm[(size_t)M_TOK * HDIM];  // 64 MB  (LN out, fp16)
__device__ float  g_resadd[(size_t)M_TOK * HDIM]; // 128 MB (pre-norm sum, fp32)
__device__ __half g_h[(size_t)M_TOK * IDIM];      // 256 MB (GELU out, fp16)
__device__ __half g_wt1[(size_t)IDIM * HDIM];     // inter_w^T  [I,H] fp16
__device__ __half g_wt2[(size_t)HDIM * IDIM];     // output_w^T [H,I] fp16

// ---------------------------------------------------------------------------
// Helpers
// ---------------------------------------------------------------------------
__device__ __forceinline__ void cp_async16(uint32_t smem_addr, const void* gptr) {
    asm volatile("cp.async.cg.shared.global [%0], [%1], 16;\n"
                 :: "r"(smem_addr), "l"(gptr));
}

__device__ __forceinline__ void ldsm4(uint32_t r[4], uint32_t addr) {
    asm volatile("ldmatrix.sync.aligned.m8n8.x4.shared.b16 {%0,%1,%2,%3}, [%4];"
                 : "=r"(r[0]), "=r"(r[1]), "=r"(r[2]), "=r"(r[3]) : "r"(addr));
}

// fp16 MMA, fp32 accumulate: D[16,8] += A[16,16] * B[16,8]
__device__ __forceinline__ void mma_f16(float c[4], const uint32_t a[4],
                                        uint32_t b0, uint32_t b1) {
    asm volatile(
        "mma.sync.aligned.m16n8k16.row.col.f32.f16.f16.f32 "
        "{%0,%1,%2,%3}, {%4,%5,%6,%7}, {%8,%9}, {%0,%1,%2,%3};\n"
        : "+f"(c[0]), "+f"(c[1]), "+f"(c[2]), "+f"(c[3])
        : "r"(a[0]), "r"(a[1]), "r"(a[2]), "r"(a[3]), "r"(b0), "r"(b1));
}

__device__ __forceinline__ float tanh_approx(float x) {
    float y;
    asm("tanh.approx.f32 %0, %1;" : "=f"(y) : "f"(x));
    return y;
}
__device__ __forceinline__ float gelu_tanh(float v) {
    float c = 0.7978845608028654f * (v + 0.044715f * v * v * v);
    return 0.5f * v * (1.0f + tanh_approx(c));
}

// ---------------------------------------------------------------------------
// Kernel 1: fused bias + residual add + LayerNorm -> fp16 xnorm + fp32 resadd
// ---------------------------------------------------------------------------
__global__ void __launch_bounds__(256) fused_add_ln(
    const float* __restrict__ inp, const float* __restrict__ resid,
    const float* __restrict__ bias, const float* __restrict__ gw,
    const float* __restrict__ gb, __half* __restrict__ xn,
    float* __restrict__ ra)
{
    const int row = blockIdx.x;
    const int t = threadIdx.x;
    const size_t base = (size_t)row * HDIM + t * 4;

    float4 x = *(const float4*)(inp + base);
    float4 r = *(const float4*)(resid + base);
    float4 b = *(const float4*)(bias + t * 4);

    float4 s;
    s.x = x.x + b.x + r.x;
    s.y = x.y + b.y + r.y;
    s.z = x.z + b.z + r.z;
    s.w = x.w + b.w + r.w;
    *(float4*)(ra + base) = s;

    float sum = s.x + s.y + s.z + s.w;
    float sq  = s.x * s.x + s.y * s.y + s.z * s.z + s.w * s.w;

    #pragma unroll
    for (int o = 16; o > 0; o >>= 1) {
        sum += __shfl_xor_sync(0xFFFFFFFFu, sum, o);
        sq  += __shfl_xor_sync(0xFFFFFFFFu, sq, o);
    }
    __shared__ float red[16];
    const int warp = t >> 5, lane = t & 31;
    if (lane == 0) { red[warp] = sum; red[8 + warp] = sq; }
    __syncthreads();
    if (t == 0) {
        float s0 = 0.f, q0 = 0.f;
        #pragma unroll
        for (int i = 0; i < 8; i++) { s0 += red[i]; q0 += red[8 + i]; }
        red[0] = s0; red[8] = q0;
    }
    __syncthreads();
    const float mean = red[0] * (1.0f / HDIM);
    const float var  = red[8] * (1.0f / HDIM) - mean * mean;
    const float rstd = rsqrtf(var + 1e-5f);

    float4 w = *(const float4*)(gw + t * 4);
    float4 be = *(const float4*)(gb + t * 4);
    float o0 = (s.x - mean) * rstd * w.x + be.x;
    float o1 = (s.y - mean) * rstd * w.y + be.y;
    float o2 = (s.z - mean) * rstd * w.z + be.z;
    float o3 = (s.w - mean) * rstd * w.w + be.w;
    __half2* xo = (__half2*)(xn + base);
    xo[0] = __floats2half2_rn(o0, o1);
    xo[1] = __floats2half2_rn(o2, o3);
}

// ---------------------------------------------------------------------------
// Kernel: 32x32 tiled transpose, fp32 in -> fp16 out (out[c][r] = in[r][c])
// ---------------------------------------------------------------------------
__global__ void __launch_bounds__(256) transpose32h(
    const float* __restrict__ in, __half* __restrict__ out, int R, int C)
{
    __shared__ float t[32][33];
    const int c0 = blockIdx.x * 32, r0 = blockIdx.y * 32;
    #pragma unroll
    for (int i = threadIdx.y; i < 32; i += 8)
        t[i][threadIdx.x] = in[(size_t)(r0 + i) * C + c0 + threadIdx.x];
    __syncthreads();
    #pragma unroll
    for (int i = threadIdx.y; i < 32; i += 8)
        out[(size_t)(c0 + i) * R + r0 + threadIdx.x] = __float2half_rn(t[threadIdx.x][i]);
}

// ---------------------------------------------------------------------------
// FP16 GEMM: C[M,N] = A[M,K] @ Bt[N,K]^T (+bias, +GELU->half or +residual->f32)
// CTA tile 128x128xBK64, 8 warps (4x2), warp tile 32x64, m16n8k16 HMMA.
// 3-stage cp.async pipeline, ONE __syncthreads per k-iter, 2 CTAs/SM
// -> 16 warps/SM (4 per SMSP) for latency hiding. Regs capped at 128/thread.
// ---------------------------------------------------------------------------
#define BM 128
#define BN 128
#define BKH 64                        // halves per K-slab (128 bytes)
#define KSTH 72                       // smem row stride in halves (64 + 8 pad)
#define A_HALVES (BM * KSTH)          // 9216
#define B_HALVES (BN * KSTH)          // 9216
#define STAGE_HALVES (A_HALVES + B_HALVES)   // 18432
#define NSTG 3
#define SMEM_BYTES (NSTG * STAGE_HALVES * 2) // 110592

template <bool GELU>
__global__ void __launch_bounds__(256, 2) gemm_f16(
    const __half* __restrict__ A, const __half* __restrict__ Bt,
    const float* __restrict__ bias, const float* __restrict__ res,
    void* __restrict__ Cv, int N, int K)
{
    extern __shared__ __half smh[];
    const uint32_t sm0 = (uint32_t)__cvta_generic_to_shared(smh);

    const int tid = threadIdx.x;
    const int warp = tid >> 5, lane = tid & 31;
    const int wm = warp >> 1, wn = warp & 1;     // 4 (M) x 2 (N)
    const int row0 = blockIdx.y * BM;
    const int col0 = blockIdx.x * BN;
    const int g = lane >> 2, tq = lane & 3;

    // ldmatrix per-thread address components (in halves)
    const int a_row = wm * 32 + (lane & 15);
    const int a_k   = (lane >> 4) * 8;
    const int b_row = wn * 64 + ((lane & 7) | ((lane >> 1) & 8));
    const int b_k   = ((lane >> 3) & 1) * 8;

    float acc[2][8][4];
    #pragma unroll
    for (int mi = 0; mi < 2; mi++)
        #pragma unroll
        for (int j = 0; j < 8; j++)
            #pragma unroll
            for (int q = 0; q < 4; q++) acc[mi][j][q] = 0.0f;

    const int nK = K / BKH;

    auto load_stage = [&](int kt, int s) {
        __half* As = smh + s * STAGE_HALVES;
        __half* Bs = As + A_HALVES;
        const __half* Ag = A + (size_t)row0 * K + kt * BKH;
        const __half* Bg = Bt + (size_t)col0 * K + kt * BKH;
        #pragma unroll
        for (int i = 0; i < 4; i++) {          // A: 1024 chunks of 16B (8 halves)
            int c = tid + 256 * i;
            int r = c >> 3, o = (c & 7) * 8;
            cp_async16((uint32_t)__cvta_generic_to_shared(As + r * KSTH + o),
                       Ag + (size_t)r * K + o);
        }
        #pragma unroll
        for (int i = 0; i < 4; i++) {          // B: 1024 chunks of 16B
            int c = tid + 256 * i;
            int r = c >> 3, o = (c & 7) * 8;
            cp_async16((uint32_t)__cvta_generic_to_shared(Bs + r * KSTH + o),
                       Bg + (size_t)r * K + o);
        }
        asm volatile("cp.async.commit_group;\n");
    };

    // prefill 2 stages (tiles 0,1 -> 2 groups)
    load_stage(0, 0);
    load_stage(1, 1);

    for (int kt = 0; kt < nK; kt++) {
        const int s = kt % NSTG;
        // tile kt complete in THIS thread (only tile kt+1's group may pend)
        asm volatile("cp.async.wait_group 1;\n");
        // publish all threads' copies of tile kt; also: everyone is done
        // reading stage (kt-1)%NSTG, which gets overwritten below
        __syncthreads();
        if (kt + 2 < nK) {
            load_stage(kt + 2, (kt + 2) % NSTG);       // commits 1 group
        } else {
            asm volatile("cp.async.commit_group;\n");  // keep group-count invariant
        }

        const uint32_t As_u = sm0 + (s * STAGE_HALVES) * 2;
        const uint32_t Bs_u = As_u + A_HALVES * 2;
        const uint32_t a_addr = As_u + (a_row * KSTH + a_k) * 2;
        const uint32_t b_addr = Bs_u + (b_row * KSTH + b_k) * 2;

        #pragma unroll
        for (int kk = 0; kk < BKH; kk += 16) {
            uint32_t af[2][4], bf[4][4];
            #pragma unroll
            for (int mi = 0; mi < 2; mi++)
                ldsm4(af[mi], a_addr + (mi * 16 * KSTH + kk) * 2);
            #pragma unroll
            for (int p = 0; p < 4; p++)
                ldsm4(bf[p], b_addr + (p * 16 * KSTH + kk) * 2);
            #pragma unroll
            for (int mi = 0; mi < 2; mi++)
                #pragma unroll
                for (int j = 0; j < 8; j++)
                    mma_f16(acc[mi][j], af[mi],
                            bf[j >> 1][(j & 1) * 2], bf[j >> 1][(j & 1) * 2 + 1]);
        }
    }

    // Epilogue: register -> gmem
    #pragma unroll
    for (int mi = 0; mi < 2; mi++) {
        const int r0 = row0 + wm * 32 + mi * 16 + g;
        const int r1 = r0 + 8;
        #pragma unroll
        for (int j = 0; j < 8; j++) {
            const int c = col0 + wn * 64 + j * 8 + tq * 2;
            const float b0 = bias[c], b1 = bias[c + 1];
            float v00 = acc[mi][j][0] + b0;
            float v01 = acc[mi][j][1] + b1;
            float v10 = acc[mi][j][2] + b0;
            float v11 = acc[mi][j][3] + b1;
            if (GELU) {
                __half* Ch = (__half*)Cv;
                v00 = gelu_tanh(v00); v01 = gelu_tanh(v01);
                v10 = gelu_tanh(v10); v11 = gelu_tanh(v11);
                *(__half2*)(Ch + (size_t)r0 * N + c) = __floats2half2_rn(v00, v01);
                *(__half2*)(Ch + (size_t)r1 * N + c) = __floats2half2_rn(v10, v11);
            } else {
                float* Cf = (float*)Cv;
                const float2 ra0 = *(const float2*)(res + (size_t)r0 * N + c);
                const float2 ra1 = *(const float2*)(res + (size_t)r1 * N + c);
                v00 += ra0.x; v01 += ra0.y;
                v10 += ra1.x; v11 += ra1.y;
                *(float2*)(Cf + (size_t)r0 * N + c) = make_float2(v00, v01);
                *(float2*)(Cf + (size_t)r1 * N + c) = make_float2(v10, v11);
            }
        }
    }
}

// ---------------------------------------------------------------------------
// Launch
// ---------------------------------------------------------------------------
extern "C" void kernel_launch(void* const* d_in, const int* in_sizes, int n_in,
                              void* d_out, int out_size)
{
    const float* input    = (const float*)d_in[0];
    const float* residual = (const float*)d_in[1];
    const float* bias     = (const float*)d_in[3];
    const float* attn_nw  = (const float*)d_in[4];
    const float* attn_nb  = (const float*)d_in[5];
    const float* inter_w  = (const float*)d_in[6];
    const float* inter_b  = (const float*)d_in[7];
    const float* output_w = (const float*)d_in[8];
    const float* output_b = (const float*)d_in[9];
    float* out = (float*)d_out;

    __half *xn, *hbuf, *wt1, *wt2;
    float *ra;
    cudaGetSymbolAddress((void**)&xn,   g_xnorm);
    cudaGetSymbolAddress((void**)&ra,   g_resadd);
    cudaGetSymbolAddress((void**)&hbuf, g_h);
    cudaGetSymbolAddress((void**)&wt1,  g_wt1);
    cudaGetSymbolAddress((void**)&wt2,  g_wt2);

    cudaFuncSetAttribute(gemm_f16<true>,
                         cudaFuncAttributeMaxDynamicSharedMemorySize, SMEM_BYTES);
    cudaFuncSetAttribute(gemm_f16<false>,
                         cudaFuncAttributeMaxDynamicSharedMemorySize, SMEM_BYTES);

    // weight transposes -> fp16 K-major (tiny)
    transpose32h<<<dim3(IDIM / 32, HDIM / 32), dim3(32, 8)>>>(inter_w,  wt1, HDIM, IDIM);
    transpose32h<<<dim3(HDIM / 32, IDIM / 32), dim3(32, 8)>>>(output_w, wt2, IDIM, HDIM);

    // 1) fused bias + residual + LN
    fused_add_ln<<<M_TOK, 256>>>(input, residual, bias, attn_nw, attn_nb, xn, ra);

    // 2) h = gelu(x @ inter_w + inter_b)  [32768,4096] fp16
    gemm_f16<true><<<dim3(IDIM / BN, M_TOK / BM), 256, SMEM_BYTES>>>(
        xn, wt1, inter_b, nullptr, hbuf, IDIM, HDIM);

    // 3) out = h @ output_w + output_b + residual_add  [32768,1024] fp32
    gemm_f16<false><<<dim3(HDIM / BN, M_TOK / BM), 256, SMEM_BYTES>>>(
        hbuf, wt2, output_b, ra, out, HDIM, IDIM);
}